// round 1
// baseline (speedup 1.0000x reference)
#include <cuda_runtime.h>
#include <math.h>

// ---------------- problem constants ----------------
#define Bv     64
#define Hd     28
#define Wd     28
#define Cc     512
#define NHEADS 16
#define WIN    7
#define SHIFTV 3
#define NTOK   49          // tokens per window
#define NWIN   16          // windows per image
#define BWIN   (Bv*NWIN)   // 1024 windows total
#define MROWS  (BWIN*NTOK) // 50176 rows
#define MLPH   2048

// ---------------- scratch (allocation-free: device globals) ----------------
__device__ float g_win[(size_t)MROWS * Cc];        // 102.8 MB  LN1+shift+partition
__device__ float g_qkv[(size_t)MROWS * 3 * Cc];    // 308 MB
__device__ float g_att[(size_t)MROWS * Cc];        // 102.8 MB  attention output (head-merged)
__device__ float g_x2 [(size_t)MROWS * Cc];        // 102.8 MB  residual after attn+proj
__device__ float g_ln2[(size_t)MROWS * Cc];        // 102.8 MB
__device__ float g_hid[(size_t)MROWS * MLPH];      // 411 MB

// Map window-token row m -> original (B, H*W) row. Same map for gather (LN1) and
// scatter (proj epilogue): shifted coordinate hh maps to original (hh+SHIFT)%28.
__device__ __forceinline__ int map_row(int m) {
    int w = m / NTOK, n = m - w * NTOK;
    int b  = w >> 4, wi = w & 15;
    int wh = wi >> 2, ww = wi & 3;
    int r  = n / 7,  c  = n - r * 7;
    int hh = wh * 7 + r;
    int w2 = ww * 7 + c;
    int oh = hh + SHIFTV; if (oh >= Hd) oh -= Hd;
    int ow = w2 + SHIFTV; if (ow >= Wd) ow -= Wd;
    return b * (Hd * Wd) + oh * Wd + ow;
}

// ---------------- LayerNorm (optionally gathering through map_row) ----------------
template<bool GATHER>
__global__ __launch_bounds__(128) void ln_kernel(const float* __restrict__ x,
                                                 const float* __restrict__ sc,
                                                 const float* __restrict__ bi,
                                                 float* __restrict__ out)
{
    int row = blockIdx.x;
    int src = GATHER ? map_row(row) : row;
    int t = threadIdx.x;
    float4 v = ((const float4*)(x + (size_t)src * Cc))[t];
    float s = v.x + v.y + v.z + v.w;
    float q = v.x*v.x + v.y*v.y + v.z*v.z + v.w*v.w;
    #pragma unroll
    for (int o = 16; o; o >>= 1) {
        s += __shfl_xor_sync(0xffffffffu, s, o);
        q += __shfl_xor_sync(0xffffffffu, q, o);
    }
    __shared__ float ss[4], qq[4], stat[2];
    int wid = t >> 5;
    if ((t & 31) == 0) { ss[wid] = s; qq[wid] = q; }
    __syncthreads();
    if (t == 0) {
        float S = ss[0] + ss[1] + ss[2] + ss[3];
        float Q = qq[0] + qq[1] + qq[2] + qq[3];
        float mean = S * (1.0f / Cc);
        float var  = Q * (1.0f / Cc) - mean * mean;
        stat[0] = mean;
        stat[1] = rsqrtf(var + 1e-5f);
    }
    __syncthreads();
    float mean = stat[0], rstd = stat[1];
    float4 sv = ((const float4*)sc)[t];
    float4 bv = ((const float4*)bi)[t];
    float4 o;
    o.x = (v.x - mean) * rstd * sv.x + bv.x;
    o.y = (v.y - mean) * rstd * sv.y + bv.y;
    o.z = (v.z - mean) * rstd * sv.z + bv.z;
    o.w = (v.w - mean) * rstd * sv.w + bv.w;
    ((float4*)(out + (size_t)row * Cc))[t] = o;
}

// ---------------- SGEMM 128x128x8, 256 threads, 8x8 per thread ----------------
enum { EPI_BIAS = 0, EPI_SCATTER = 1, EPI_GELU = 2, EPI_RESID = 3 };

template<int EPI>
__global__ __launch_bounds__(256) void sgemm(const float* __restrict__ A,
                                             const float* __restrict__ Bm,
                                             const float* __restrict__ bias,
                                             const float* __restrict__ R,
                                             float* __restrict__ C,
                                             int M, int N, int K)
{
    __shared__ float As[8][128];
    __shared__ float Bs[8][128];
    const int tid  = threadIdx.x;
    const int row0 = blockIdx.y * 128;
    const int col0 = blockIdx.x * 128;
    const int ty = tid >> 4, tx = tid & 15;
    const int arow = tid >> 1, acol = (tid & 1) * 4;
    const int brow = tid >> 5, bcol = (tid & 31) * 4;

    const float* Ap = A  + (size_t)(row0 + arow) * K + acol;
    const float* Bp = Bm + (size_t)brow * N + col0 + bcol;

    float acc[8][8] = {};
    for (int k0 = 0; k0 < K; k0 += 8) {
        float4 av = *(const float4*)(Ap + k0);
        As[acol + 0][arow] = av.x;
        As[acol + 1][arow] = av.y;
        As[acol + 2][arow] = av.z;
        As[acol + 3][arow] = av.w;
        *(float4*)(&Bs[brow][bcol]) = *(const float4*)(Bp + (size_t)k0 * N);
        __syncthreads();
        #pragma unroll
        for (int k = 0; k < 8; k++) {
            float ar[8], br[8];
            #pragma unroll
            for (int i = 0; i < 8; i++) ar[i] = As[k][ty * 8 + i];
            #pragma unroll
            for (int j = 0; j < 8; j++) br[j] = Bs[k][tx * 8 + j];
            #pragma unroll
            for (int i = 0; i < 8; i++)
                #pragma unroll
                for (int j = 0; j < 8; j++)
                    acc[i][j] += ar[i] * br[j];
        }
        __syncthreads();
    }

    float bfrag[8];
    #pragma unroll
    for (int j = 0; j < 8; j++) bfrag[j] = bias[col0 + tx * 8 + j];

    #pragma unroll
    for (int i = 0; i < 8; i++) {
        int m = row0 + ty * 8 + i;
        int drow = (EPI == EPI_SCATTER) ? map_row(m) : m;
        float* cp = C + (size_t)drow * N + col0 + tx * 8;
        const float* rp = (EPI == EPI_SCATTER || EPI == EPI_RESID)
                          ? (R + (size_t)drow * N + col0 + tx * 8) : nullptr;
        float vals[8];
        #pragma unroll
        for (int j = 0; j < 8; j++) {
            float v = acc[i][j] + bfrag[j];
            if (EPI == EPI_GELU) {
                float u = v;
                v = 0.5f * u * (1.0f + tanhf(0.7978845608f * (u + 0.044715f * u * u * u)));
            }
            if (EPI == EPI_SCATTER || EPI == EPI_RESID) v += rp[j];
            vals[j] = v;
        }
        *(float4*)cp       = make_float4(vals[0], vals[1], vals[2], vals[3]);
        *((float4*)cp + 1) = make_float4(vals[4], vals[5], vals[6], vals[7]);
    }
}

// ---------------- windowed attention: one block per (window, head) ----------------
__global__ __launch_bounds__(256) void attn_kernel(const float* __restrict__ qkv,
                                                   const float* __restrict__ rpbt,
                                                   float* __restrict__ out)
{
    int w = blockIdx.x >> 4;
    int h = blockIdx.x & 15;
    __shared__ float q[NTOK][33], k[NTOK][33], v[NTOK][33];
    __shared__ float att[NTOK][52];
    int tid = threadIdx.x;

    const float* base = qkv + (size_t)w * NTOK * (3 * Cc) + h * 32;
    for (int p = tid; p < NTOK * 32; p += 256) {
        int i = p >> 5, d = p & 31;
        const float* rp = base + (size_t)i * (3 * Cc) + d;
        q[i][d] = rp[0] * 0.1767766953f;   // 1/sqrt(32)
        k[i][d] = rp[512];
        v[i][d] = rp[1024];
    }
    __syncthreads();

    int wi = w & 15;
    int wh = wi >> 2, ww = wi & 3;

    for (int p = tid; p < NTOK * NTOK; p += 256) {
        int i = p / NTOK, j = p - i * NTOK;
        float s = 0.f;
        #pragma unroll
        for (int d = 0; d < 32; d++) s += q[i][d] * k[j][d];
        int ri = i / 7, ci = i - ri * 7;
        int rj = j / 7, cj = j - rj * 7;
        // relative position bias (closed-form index, table lookup in rpbt)
        int bidx = (ri - rj + 6) * 13 + (ci - cj + 6);
        s += rpbt[bidx * NHEADS + h];
        // shift mask (closed form): region code on shifted-image coords
        int hi = wh * 7 + ri, wwi = ww * 7 + ci;
        int hj = wh * 7 + rj, wwj = ww * 7 + cj;
        int cnti = (hi >= 25 ? 2 : (hi >= 21 ? 1 : 0)) * 3 + (wwi >= 25 ? 2 : (wwi >= 21 ? 1 : 0));
        int cntj = (hj >= 25 ? 2 : (hj >= 21 ? 1 : 0)) * 3 + (wwj >= 25 ? 2 : (wwj >= 21 ? 1 : 0));
        if (cnti != cntj) s -= 100.0f;
        att[i][j] = s;
    }
    __syncthreads();

    if (tid < NTOK) {
        float mx = -1e30f;
        #pragma unroll
        for (int j = 0; j < NTOK; j++) mx = fmaxf(mx, att[tid][j]);
        float sum = 0.f;
        #pragma unroll
        for (int j = 0; j < NTOK; j++) {
            float e = __expf(att[tid][j] - mx);
            att[tid][j] = e;
            sum += e;
        }
        float inv = 1.0f / sum;
        #pragma unroll
        for (int j = 0; j < NTOK; j++) att[tid][j] *= inv;
    }
    __syncthreads();

    float* ob = out + (size_t)w * NTOK * Cc + h * 32;
    for (int p = tid; p < NTOK * 32; p += 256) {
        int i = p >> 5, d = p & 31;
        float s = 0.f;
        #pragma unroll
        for (int j = 0; j < NTOK; j++) s += att[i][j] * v[j][d];
        ob[(size_t)i * Cc + d] = s;
    }
}

// ---------------- host launch ----------------
extern "C" void kernel_launch(void* const* d_in, const int* in_sizes, int n_in,
                              void* d_out, int out_size)
{
    const float* x      = (const float*)d_in[0];
    const float* qkv_w  = (const float*)d_in[1];
    const float* qkv_b  = (const float*)d_in[2];
    const float* proj_w = (const float*)d_in[3];
    const float* proj_b = (const float*)d_in[4];
    const float* rpbt   = (const float*)d_in[5];
    const float* n1_s   = (const float*)d_in[6];
    const float* n1_b   = (const float*)d_in[7];
    const float* n2_s   = (const float*)d_in[8];
    const float* n2_b   = (const float*)d_in[9];
    const float* fc1_w  = (const float*)d_in[10];
    const float* fc1_b  = (const float*)d_in[11];
    const float* fc2_w  = (const float*)d_in[12];
    const float* fc2_b  = (const float*)d_in[13];
    float* outp = (float*)d_out;

    float *p_win, *p_qkv, *p_att, *p_x2, *p_ln2, *p_hid;
    cudaGetSymbolAddress((void**)&p_win, g_win);
    cudaGetSymbolAddress((void**)&p_qkv, g_qkv);
    cudaGetSymbolAddress((void**)&p_att, g_att);
    cudaGetSymbolAddress((void**)&p_x2,  g_x2);
    cudaGetSymbolAddress((void**)&p_ln2, g_ln2);
    cudaGetSymbolAddress((void**)&p_hid, g_hid);

    // 1) LN1 + cyclic shift + window partition
    ln_kernel<true><<<MROWS, 128>>>(x, n1_s, n1_b, p_win);

    // 2) QKV GEMM: (50176 x 512) @ (512 x 1536) + bias
    sgemm<EPI_BIAS><<<dim3(1536 / 128, MROWS / 128), 256>>>(
        p_win, qkv_w, qkv_b, nullptr, p_qkv, MROWS, 3 * Cc, Cc);

    // 3) windowed attention (bias + shift mask + softmax + AV)
    attn_kernel<<<BWIN * NHEADS, 256>>>(p_qkv, rpbt, p_att);

    // 4) proj GEMM + window-reverse scatter + residual add with original x
    sgemm<EPI_SCATTER><<<dim3(Cc / 128, MROWS / 128), 256>>>(
        p_att, proj_w, proj_b, x, p_x2, MROWS, Cc, Cc);

    // 5) LN2
    ln_kernel<false><<<MROWS, 128>>>(p_x2, n2_s, n2_b, p_ln2);

    // 6) fc1 GEMM + GELU
    sgemm<EPI_GELU><<<dim3(MLPH / 128, MROWS / 128), 256>>>(
        p_ln2, fc1_w, fc1_b, nullptr, p_hid, MROWS, MLPH, Cc);

    // 7) fc2 GEMM + bias + residual -> d_out
    sgemm<EPI_RESID><<<dim3(Cc / 128, MROWS / 128), 256>>>(
        p_hid, fc2_w, fc2_b, p_x2, outp, MROWS, Cc, MLPH);
}

// round 3
// speedup vs baseline: 3.0520x; 3.0520x over previous
#include <cuda_runtime.h>
#include <cuda.h>
#include <math.h>
#include <stdint.h>

// ---------------- problem constants ----------------
#define Bv     64
#define Hd     28
#define Wd     28
#define Cc     512
#define NHEADS 16
#define WIN    7
#define SHIFTV 3
#define NTOK   49
#define NWIN   16
#define BWIN   (Bv*NWIN)
#define MROWS  (BWIN*NTOK)   // 50176
#define MLPH   2048
#define STAGES 4

// ---------------- scratch (allocation-free: device globals) ----------------
__device__ float g_win[(size_t)MROWS * Cc];
__device__ float g_qkv[(size_t)MROWS * 3 * Cc];
__device__ float g_att[(size_t)MROWS * Cc];
__device__ float g_x2 [(size_t)MROWS * Cc];
__device__ float g_ln2[(size_t)MROWS * Cc];
__device__ float g_hid[(size_t)MROWS * MLPH];
// transposed (+tf32-rounded) weights, [N][K] K-major
__device__ float g_wqkvT[(size_t)(3*Cc) * Cc];
__device__ float g_wprojT[(size_t)Cc * Cc];
__device__ float g_wfc1T[(size_t)MLPH * Cc];
__device__ float g_wfc2T[(size_t)Cc * MLPH];

// ---------------- helpers ----------------
__device__ __forceinline__ uint32_t smem_u32(const void* p) {
    uint32_t a;
    asm("{ .reg .u64 t; cvta.to.shared.u64 t, %1; cvt.u32.u64 %0, t; }" : "=r"(a) : "l"(p));
    return a;
}
__device__ __forceinline__ float to_tf32(float x) {
    float r; asm("cvt.rna.tf32.f32 %0, %1;" : "=f"(r) : "f"(x)); return r;
}
__device__ __forceinline__ void ldsm4(uint32_t* r, uint32_t addr) {
    asm volatile("ldmatrix.sync.aligned.m8n8.x4.b16 {%0,%1,%2,%3}, [%4];"
                 : "=r"(r[0]), "=r"(r[1]), "=r"(r[2]), "=r"(r[3]) : "r"(addr));
}
__device__ __forceinline__ void mma_tf32(float* c, const uint32_t* a, const uint32_t* b) {
    asm volatile("mma.sync.aligned.m16n8k8.row.col.f32.tf32.tf32.f32 "
                 "{%0,%1,%2,%3}, {%4,%5,%6,%7}, {%8,%9}, {%0,%1,%2,%3};"
                 : "+f"(c[0]), "+f"(c[1]), "+f"(c[2]), "+f"(c[3])
                 : "r"(a[0]), "r"(a[1]), "r"(a[2]), "r"(a[3]), "r"(b[0]), "r"(b[1]));
}

// ---------------- row map: window token -> original (B, H*W) row ----------------
__device__ __forceinline__ int map_row(int m) {
    int w = m / NTOK, n = m - w * NTOK;
    int b  = w >> 4, wi = w & 15;
    int wh = wi >> 2, ww = wi & 3;
    int r  = n / 7,  c  = n - r * 7;
    int oh = wh * 7 + r + SHIFTV; if (oh >= Hd) oh -= Hd;
    int ow = ww * 7 + c + SHIFTV; if (ow >= Wd) ow -= Wd;
    return b * (Hd * Wd) + oh * Wd + ow;
}

// ---------------- LayerNorm ----------------
template<bool GATHER, bool ROUND>
__global__ __launch_bounds__(128) void ln_kernel(const float* __restrict__ x,
                                                 const float* __restrict__ sc,
                                                 const float* __restrict__ bi,
                                                 float* __restrict__ out)
{
    int row = blockIdx.x;
    int src = GATHER ? map_row(row) : row;
    int t = threadIdx.x;
    float4 v = ((const float4*)(x + (size_t)src * Cc))[t];
    float s = v.x + v.y + v.z + v.w;
    float q = v.x*v.x + v.y*v.y + v.z*v.z + v.w*v.w;
    #pragma unroll
    for (int o = 16; o; o >>= 1) {
        s += __shfl_xor_sync(0xffffffffu, s, o);
        q += __shfl_xor_sync(0xffffffffu, q, o);
    }
    __shared__ float ss[4], qq[4], stat[2];
    int wid = t >> 5;
    if ((t & 31) == 0) { ss[wid] = s; qq[wid] = q; }
    __syncthreads();
    if (t == 0) {
        float S = ss[0] + ss[1] + ss[2] + ss[3];
        float Q = qq[0] + qq[1] + qq[2] + qq[3];
        float mean = S * (1.0f / Cc);
        float var  = Q * (1.0f / Cc) - mean * mean;
        stat[0] = mean; stat[1] = rsqrtf(var + 1e-5f);
    }
    __syncthreads();
    float mean = stat[0], rstd = stat[1];
    float4 sv = ((const float4*)sc)[t];
    float4 bv = ((const float4*)bi)[t];
    float4 o;
    o.x = (v.x - mean) * rstd * sv.x + bv.x;
    o.y = (v.y - mean) * rstd * sv.y + bv.y;
    o.z = (v.z - mean) * rstd * sv.z + bv.z;
    o.w = (v.w - mean) * rstd * sv.w + bv.w;
    if (ROUND) { o.x = to_tf32(o.x); o.y = to_tf32(o.y); o.z = to_tf32(o.z); o.w = to_tf32(o.w); }
    ((float4*)(out + (size_t)row * Cc))[t] = o;
}

// ---------------- weight transpose [K][N] -> [N][K], tf32-rounded ----------------
__global__ __launch_bounds__(256) void transpose_rt(const float* __restrict__ in,
                                                    float* __restrict__ out, int K, int N)
{
    __shared__ float t[32][33];
    int k0 = blockIdx.y * 32, n0 = blockIdx.x * 32;
    int tx = threadIdx.x & 31, ty = threadIdx.x >> 5;
    #pragma unroll
    for (int i = ty; i < 32; i += 8) t[i][tx] = in[(size_t)(k0 + i) * N + n0 + tx];
    __syncthreads();
    #pragma unroll
    for (int i = ty; i < 32; i += 8)
        out[(size_t)(n0 + i) * K + k0 + tx] = to_tf32(t[tx][i]);
}

// ---------------- tf32 mma.sync GEMM: C[M,N] = A[M,K] @ Bt[N,K]^T + epi ----------------
// CTA tile 128x128, k-chunk 32, 8 warps (4m x 2n), warp tile 32x64.
enum { EPI_BIAS = 0, EPI_SCATTER = 1, EPI_GELU = 2, EPI_RESID = 3 };

template<int EPI>
__global__ __launch_bounds__(256) void gemm_tc(const float* __restrict__ A,
                                               const float* __restrict__ Bt,
                                               const float* __restrict__ bias,
                                               const float* __restrict__ R,
                                               float* __restrict__ C,
                                               int M, int N, int K)
{
    extern __shared__ char smem[];
    const uint32_t sb = smem_u32(smem);
    const int tid = threadIdx.x;
    const int wid = tid >> 5;
    const int lid = tid & 31;
    const int wm = wid & 3;          // warp row  (4)
    const int wn = wid >> 2;         // warp col  (2)

    const int row0 = blockIdx.y * 128;
    const int col0 = blockIdx.x * 128;
    const int NC = K >> 5;

    // cp.async producer: 128 rows x 32 floats per operand per chunk
    auto load_chunk = [&](int c) {
        const uint32_t st = sb + (uint32_t)(c % STAGES) * 32768u;
        const int k0 = c << 5;
        #pragma unroll
        for (int p = 0; p < 4; p++) {
            int l = p * 256 + tid; int r = l >> 3, u = l & 7;
            const float* g = A + (size_t)(row0 + r) * K + k0 + u * 4;
            uint32_t off = (uint32_t)r * 128u + (uint32_t)((u ^ (r & 7)) << 4);
            asm volatile("cp.async.cg.shared.global [%0], [%1], 16;" :: "r"(st + off), "l"(g));
        }
        #pragma unroll
        for (int p = 0; p < 4; p++) {
            int l = p * 256 + tid; int r = l >> 3, u = l & 7;
            const float* g = Bt + (size_t)(col0 + r) * K + k0 + u * 4;
            uint32_t off = 16384u + (uint32_t)r * 128u + (uint32_t)((u ^ (r & 7)) << 4);
            asm volatile("cp.async.cg.shared.global [%0], [%1], 16;" :: "r"(st + off), "l"(g));
        }
        asm volatile("cp.async.commit_group;" ::: "memory");
    };

    // lane-derived ldmatrix address components
    const uint32_t swz   = lid & 7;
    const uint32_t a_row = (lid & 7) + ((lid >> 3) & 1) * 8;   // 0..15 within m16 tile
    const uint32_t a_khi = (lid >> 4);                          // k-group select
    const uint32_t b_row = ((lid >> 4) & 1) * 8 + (lid & 7);    // 0..15 within n16 block
    const uint32_t b_khi = (lid >> 3) & 1;

    float acc[2][8][4];
    #pragma unroll
    for (int mt = 0; mt < 2; mt++)
        #pragma unroll
        for (int nt = 0; nt < 8; nt++)
            #pragma unroll
            for (int j = 0; j < 4; j++) acc[mt][nt][j] = 0.f;

    // prologue: STAGES-1 chunks in flight
    for (int c = 0; c < STAGES - 1; c++) load_chunk(c);

    for (int c = 0; c < NC; c++) {
        asm volatile("cp.async.wait_group %0;" :: "n"(STAGES - 2) : "memory");
        __syncthreads();

        // keep committed-group count invariant; overwrites stage read in iter c-1
        if (c + STAGES - 1 < NC) load_chunk(c + STAGES - 1);
        else asm volatile("cp.async.commit_group;" ::: "memory");

        const uint32_t sA = sb + (uint32_t)(c % STAGES) * 32768u;
        const uint32_t sB = sA + 16384u;

        #pragma unroll
        for (int ks = 0; ks < 4; ks++) {
            uint32_t a[2][4];
            #pragma unroll
            for (int mt = 0; mt < 2; mt++) {
                uint32_t row = (uint32_t)(wm * 32 + mt * 16) + a_row;
                uint32_t kg  = (uint32_t)(ks * 2) + a_khi;
                ldsm4(a[mt], sA + row * 128u + ((kg ^ swz) << 4));
            }
            uint32_t b[8][2];
            #pragma unroll
            for (int i = 0; i < 4; i++) {
                uint32_t row = (uint32_t)(wn * 64 + i * 16) + b_row;
                uint32_t kg  = (uint32_t)(ks * 2) + b_khi;
                uint32_t r4[4];
                ldsm4(r4, sB + row * 128u + ((kg ^ swz) << 4));
                b[2*i][0]   = r4[0]; b[2*i][1]   = r4[1];
                b[2*i+1][0] = r4[2]; b[2*i+1][1] = r4[3];
            }
            #pragma unroll
            for (int mt = 0; mt < 2; mt++)
                #pragma unroll
                for (int nt = 0; nt < 8; nt++)
                    mma_tf32(acc[mt][nt], a[mt], b[nt]);
        }
        __syncthreads();
    }

    // ---------------- epilogue ----------------
    const int cbase = col0 + wn * 64 + (lid & 3) * 2;
    float2 bf[8];
    #pragma unroll
    for (int nt = 0; nt < 8; nt++) bf[nt] = *(const float2*)(bias + cbase + nt * 8);

    #pragma unroll
    for (int mt = 0; mt < 2; mt++) {
        #pragma unroll
        for (int h = 0; h < 2; h++) {
            int m = row0 + wm * 32 + mt * 16 + h * 8 + (lid >> 2);
            int drow = (EPI == EPI_SCATTER) ? map_row(m) : m;
            float* cp = C + (size_t)drow * N + cbase;
            const float* rp = (EPI == EPI_SCATTER || EPI == EPI_RESID)
                              ? (R + (size_t)drow * N + cbase) : nullptr;
            #pragma unroll
            for (int nt = 0; nt < 8; nt++) {
                float vx = acc[mt][nt][h * 2 + 0] + bf[nt].x;
                float vy = acc[mt][nt][h * 2 + 1] + bf[nt].y;
                if (EPI == EPI_GELU) {
                    float u = vx;
                    vx = 0.5f * u * (1.0f + tanhf(0.7978845608f * (u + 0.044715f * u * u * u)));
                    vx = to_tf32(vx);
                    u = vy;
                    vy = 0.5f * u * (1.0f + tanhf(0.7978845608f * (u + 0.044715f * u * u * u)));
                    vy = to_tf32(vy);
                }
                if (EPI == EPI_SCATTER || EPI == EPI_RESID) {
                    float2 rv = *(const float2*)(rp + nt * 8);
                    vx += rv.x; vy += rv.y;
                }
                *(float2*)(cp + nt * 8) = make_float2(vx, vy);
            }
        }
    }
}

// ---------------- windowed attention ----------------
__global__ __launch_bounds__(256) void attn_kernel(const float* __restrict__ qkv,
                                                   const float* __restrict__ rpbt,
                                                   float* __restrict__ out)
{
    int w = blockIdx.x >> 4;
    int h = blockIdx.x & 15;
    __shared__ float q[NTOK][33], k[NTOK][33], v[NTOK][33];
    __shared__ float att[NTOK][52];
    int tid = threadIdx.x;

    const float* base = qkv + (size_t)w * NTOK * (3 * Cc) + h * 32;
    for (int p = tid; p < NTOK * 32; p += 256) {
        int i = p >> 5, d = p & 31;
        const float* rp = base + (size_t)i * (3 * Cc) + d;
        q[i][d] = rp[0] * 0.1767766953f;
        k[i][d] = rp[512];
        v[i][d] = rp[1024];
    }
    __syncthreads();

    int wi = w & 15;
    int wh = wi >> 2, ww = wi & 3;

    for (int p = tid; p < NTOK * NTOK; p += 256) {
        int i = p / NTOK, j = p - i * NTOK;
        float s = 0.f;
        #pragma unroll
        for (int d = 0; d < 32; d++) s += q[i][d] * k[j][d];
        int ri = i / 7, ci = i - ri * 7;
        int rj = j / 7, cj = j - rj * 7;
        int bidx = (ri - rj + 6) * 13 + (ci - cj + 6);
        s += rpbt[bidx * NHEADS + h];
        int hi = wh * 7 + ri, wwi = ww * 7 + ci;
        int hj = wh * 7 + rj, wwj = ww * 7 + cj;
        int cnti = (hi >= 25 ? 2 : (hi >= 21 ? 1 : 0)) * 3 + (wwi >= 25 ? 2 : (wwi >= 21 ? 1 : 0));
        int cntj = (hj >= 25 ? 2 : (hj >= 21 ? 1 : 0)) * 3 + (wwj >= 25 ? 2 : (wwj >= 21 ? 1 : 0));
        if (cnti != cntj) s -= 100.0f;
        att[i][j] = s;
    }
    __syncthreads();

    if (tid < NTOK) {
        float mx = -1e30f;
        #pragma unroll
        for (int j = 0; j < NTOK; j++) mx = fmaxf(mx, att[tid][j]);
        float sum = 0.f;
        #pragma unroll
        for (int j = 0; j < NTOK; j++) {
            float e = __expf(att[tid][j] - mx);
            att[tid][j] = e;
            sum += e;
        }
        float inv = 1.0f / sum;
        #pragma unroll
        for (int j = 0; j < NTOK; j++) att[tid][j] *= inv;
    }
    __syncthreads();

    float* ob = out + (size_t)w * NTOK * Cc + h * 32;
    for (int p = tid; p < NTOK * 32; p += 256) {
        int i = p >> 5, d = p & 31;
        float s = 0.f;
        #pragma unroll
        for (int j = 0; j < NTOK; j++) s += att[i][j] * v[j][d];
        ob[(size_t)i * Cc + d] = to_tf32(s);
    }
}

// ---------------- host launch ----------------
extern "C" void kernel_launch(void* const* d_in, const int* in_sizes, int n_in,
                              void* d_out, int out_size)
{
    const float* x      = (const float*)d_in[0];
    const float* qkv_w  = (const float*)d_in[1];
    const float* qkv_b  = (const float*)d_in[2];
    const float* proj_w = (const float*)d_in[3];
    const float* proj_b = (const float*)d_in[4];
    const float* rpbt   = (const float*)d_in[5];
    const float* n1_s   = (const float*)d_in[6];
    const float* n1_b   = (const float*)d_in[7];
    const float* n2_s   = (const float*)d_in[8];
    const float* n2_b   = (const float*)d_in[9];
    const float* fc1_w  = (const float*)d_in[10];
    const float* fc1_b  = (const float*)d_in[11];
    const float* fc2_w  = (const float*)d_in[12];
    const float* fc2_b  = (const float*)d_in[13];
    float* outp = (float*)d_out;

    float *p_win, *p_qkv, *p_att, *p_x2, *p_ln2, *p_hid;
    float *p_wqkvT, *p_wprojT, *p_wfc1T, *p_wfc2T;
    cudaGetSymbolAddress((void**)&p_win, g_win);
    cudaGetSymbolAddress((void**)&p_qkv, g_qkv);
    cudaGetSymbolAddress((void**)&p_att, g_att);
    cudaGetSymbolAddress((void**)&p_x2,  g_x2);
    cudaGetSymbolAddress((void**)&p_ln2, g_ln2);
    cudaGetSymbolAddress((void**)&p_hid, g_hid);
    cudaGetSymbolAddress((void**)&p_wqkvT, g_wqkvT);
    cudaGetSymbolAddress((void**)&p_wprojT, g_wprojT);
    cudaGetSymbolAddress((void**)&p_wfc1T, g_wfc1T);
    cudaGetSymbolAddress((void**)&p_wfc2T, g_wfc2T);

    const int SMEM_BYTES = STAGES * 32768;
    cudaFuncSetAttribute(gemm_tc<EPI_BIAS>,    cudaFuncAttributeMaxDynamicSharedMemorySize, SMEM_BYTES);
    cudaFuncSetAttribute(gemm_tc<EPI_SCATTER>, cudaFuncAttributeMaxDynamicSharedMemorySize, SMEM_BYTES);
    cudaFuncSetAttribute(gemm_tc<EPI_GELU>,    cudaFuncAttributeMaxDynamicSharedMemorySize, SMEM_BYTES);
    cudaFuncSetAttribute(gemm_tc<EPI_RESID>,   cudaFuncAttributeMaxDynamicSharedMemorySize, SMEM_BYTES);

    // 0) weight transposes (tf32-rounded), [K][N] -> [N][K]
    transpose_rt<<<dim3(3*Cc/32, Cc/32),  256>>>(qkv_w,  p_wqkvT,  Cc,   3*Cc);
    transpose_rt<<<dim3(Cc/32,   Cc/32),  256>>>(proj_w, p_wprojT, Cc,   Cc);
    transpose_rt<<<dim3(MLPH/32, Cc/32),  256>>>(fc1_w,  p_wfc1T,  Cc,   MLPH);
    transpose_rt<<<dim3(Cc/32,   MLPH/32),256>>>(fc2_w,  p_wfc2T,  MLPH, Cc);

    // 1) LN1 + shift + window partition (tf32-rounded A)
    ln_kernel<true, true><<<MROWS, 128>>>(x, n1_s, n1_b, p_win);

    // 2) QKV GEMM
    gemm_tc<EPI_BIAS><<<dim3(3*Cc/128, MROWS/128), 256, SMEM_BYTES>>>(
        p_win, p_wqkvT, qkv_b, nullptr, p_qkv, MROWS, 3*Cc, Cc);

    // 3) windowed attention
    attn_kernel<<<BWIN * NHEADS, 256>>>(p_qkv, rpbt, p_att);

    // 4) proj GEMM + window-reverse scatter + residual
    gemm_tc<EPI_SCATTER><<<dim3(Cc/128, MROWS/128), 256, SMEM_BYTES>>>(
        p_att, p_wprojT, proj_b, x, p_x2, MROWS, Cc, Cc);

    // 5) LN2 (tf32-rounded A)
    ln_kernel<false, true><<<MROWS, 128>>>(p_x2, n2_s, n2_b, p_ln2);

    // 6) fc1 GEMM + GELU (tf32-rounded out)
    gemm_tc<EPI_GELU><<<dim3(MLPH/128, MROWS/128), 256, SMEM_BYTES>>>(
        p_ln2, p_wfc1T, fc1_b, nullptr, p_hid, MROWS, MLPH, Cc);

    // 7) fc2 GEMM + bias + residual -> out
    gemm_tc<EPI_RESID><<<dim3(Cc/128, MROWS/128), 256, SMEM_BYTES>>>(
        p_hid, p_wfc2T, fc2_b, p_x2, outp, MROWS, Cc, MLPH);
}

// round 4
// speedup vs baseline: 3.4141x; 1.1186x over previous
#include <cuda_runtime.h>
#include <cuda.h>
#include <math.h>
#include <stdint.h>

// ---------------- problem constants ----------------
#define Bv     64
#define Hd     28
#define Wd     28
#define Cc     512
#define NHEADS 16
#define WIN    7
#define SHIFTV 3
#define NTOK   49
#define NWIN   16
#define BWIN   (Bv*NWIN)
#define MROWS  (BWIN*NTOK)   // 50176
#define MLPH   2048
#define STAGES 3

// ---------------- scratch (allocation-free: device globals) ----------------
__device__ float g_win[(size_t)MROWS * Cc];
__device__ float g_qkv[(size_t)MROWS * 3 * Cc];
__device__ float g_att[(size_t)MROWS * Cc];
__device__ float g_x2 [(size_t)MROWS * Cc];
__device__ float g_ln2[(size_t)MROWS * Cc];
__device__ float g_hid[(size_t)MROWS * MLPH];
// transposed (+tf32-rounded) weights, [N][K] K-major
__device__ float g_wqkvT[(size_t)(3*Cc) * Cc];
__device__ float g_wprojT[(size_t)Cc * Cc];
__device__ float g_wfc1T[(size_t)MLPH * Cc];
__device__ float g_wfc2T[(size_t)Cc * MLPH];

// ---------------- helpers ----------------
__device__ __forceinline__ uint32_t smem_u32(const void* p) {
    uint32_t a;
    asm("{ .reg .u64 t; cvta.to.shared.u64 t, %1; cvt.u32.u64 %0, t; }" : "=r"(a) : "l"(p));
    return a;
}
__device__ __forceinline__ float to_tf32(float x) {
    float r; asm("cvt.rna.tf32.f32 %0, %1;" : "=f"(r) : "f"(x)); return r;
}
__device__ __forceinline__ void ldsm4(uint32_t* r, uint32_t addr) {
    asm volatile("ldmatrix.sync.aligned.m8n8.x4.b16 {%0,%1,%2,%3}, [%4];"
                 : "=r"(r[0]), "=r"(r[1]), "=r"(r[2]), "=r"(r[3]) : "r"(addr));
}
__device__ __forceinline__ void mma_tf32(float* c, const uint32_t* a, const uint32_t* b) {
    asm volatile("mma.sync.aligned.m16n8k8.row.col.f32.tf32.tf32.f32 "
                 "{%0,%1,%2,%3}, {%4,%5,%6,%7}, {%8,%9}, {%0,%1,%2,%3};"
                 : "+f"(c[0]), "+f"(c[1]), "+f"(c[2]), "+f"(c[3])
                 : "r"(a[0]), "r"(a[1]), "r"(a[2]), "r"(a[3]), "r"(b[0]), "r"(b[1]));
}

// ---------------- row map: window token -> original (B, H*W) row ----------------
__device__ __forceinline__ int map_row(int m) {
    int w = m / NTOK, n = m - w * NTOK;
    int b  = w >> 4, wi = w & 15;
    int wh = wi >> 2, ww = wi & 3;
    int r  = n / 7,  c  = n - r * 7;
    int oh = wh * 7 + r + SHIFTV; if (oh >= Hd) oh -= Hd;
    int ow = ww * 7 + c + SHIFTV; if (ow >= Wd) ow -= Wd;
    return b * (Hd * Wd) + oh * Wd + ow;
}

// ---------------- LayerNorm ----------------
template<bool GATHER, bool ROUND>
__global__ __launch_bounds__(128) void ln_kernel(const float* __restrict__ x,
                                                 const float* __restrict__ sc,
                                                 const float* __restrict__ bi,
                                                 float* __restrict__ out)
{
    int row = blockIdx.x;
    int src = GATHER ? map_row(row) : row;
    int t = threadIdx.x;
    float4 v = ((const float4*)(x + (size_t)src * Cc))[t];
    float s = v.x + v.y + v.z + v.w;
    float q = v.x*v.x + v.y*v.y + v.z*v.z + v.w*v.w;
    #pragma unroll
    for (int o = 16; o; o >>= 1) {
        s += __shfl_xor_sync(0xffffffffu, s, o);
        q += __shfl_xor_sync(0xffffffffu, q, o);
    }
    __shared__ float ss[4], qq[4], stat[2];
    int wid = t >> 5;
    if ((t & 31) == 0) { ss[wid] = s; qq[wid] = q; }
    __syncthreads();
    if (t == 0) {
        float S = ss[0] + ss[1] + ss[2] + ss[3];
        float Q = qq[0] + qq[1] + qq[2] + qq[3];
        float mean = S * (1.0f / Cc);
        float var  = Q * (1.0f / Cc) - mean * mean;
        stat[0] = mean; stat[1] = rsqrtf(var + 1e-5f);
    }
    __syncthreads();
    float mean = stat[0], rstd = stat[1];
    float4 sv = ((const float4*)sc)[t];
    float4 bv = ((const float4*)bi)[t];
    float4 o;
    o.x = (v.x - mean) * rstd * sv.x + bv.x;
    o.y = (v.y - mean) * rstd * sv.y + bv.y;
    o.z = (v.z - mean) * rstd * sv.z + bv.z;
    o.w = (v.w - mean) * rstd * sv.w + bv.w;
    if (ROUND) { o.x = to_tf32(o.x); o.y = to_tf32(o.y); o.z = to_tf32(o.z); o.w = to_tf32(o.w); }
    ((float4*)(out + (size_t)row * Cc))[t] = o;
}

// ---------------- weight transpose [K][N] -> [N][K], tf32-rounded ----------------
__global__ __launch_bounds__(256) void transpose_rt(const float* __restrict__ in,
                                                    float* __restrict__ out, int K, int N)
{
    __shared__ float t[32][33];
    int k0 = blockIdx.y * 32, n0 = blockIdx.x * 32;
    int tx = threadIdx.x & 31, ty = threadIdx.x >> 5;
    #pragma unroll
    for (int i = ty; i < 32; i += 8) t[i][tx] = in[(size_t)(k0 + i) * N + n0 + tx];
    __syncthreads();
    #pragma unroll
    for (int i = ty; i < 32; i += 8)
        out[(size_t)(n0 + i) * K + k0 + tx] = to_tf32(t[tx][i]);
}

// ---------------- tf32 mma.sync GEMM: C[M,N] = A[M,K] @ Bt[N,K]^T + epi ----------------
// CTA tile 128x128, k-chunk 32, 8 warps (4m x 2n), warp tile 32x64, 3-stage, 2 CTAs/SM.
enum { EPI_BIAS = 0, EPI_SCATTER = 1, EPI_GELU = 2, EPI_RESID = 3 };

template<int EPI>
__global__ __launch_bounds__(256, 2) void gemm_tc(const float* __restrict__ A,
                                                  const float* __restrict__ Bt,
                                                  const float* __restrict__ bias,
                                                  const float* __restrict__ R,
                                                  float* __restrict__ C,
                                                  int M, int N, int K)
{
    extern __shared__ char smem[];
    const uint32_t sb = smem_u32(smem);
    const int tid = threadIdx.x;
    const int wid = tid >> 5;
    const int lid = tid & 31;
    const int wm = wid & 3;          // warp row  (4)
    const int wn = wid >> 2;         // warp col  (2)

    const int row0 = blockIdx.y * 128;
    const int col0 = blockIdx.x * 128;
    const int NC = K >> 5;

    // cp.async producer: 128 rows x 32 floats per operand per chunk
    auto load_chunk = [&](int c) {
        const uint32_t st = sb + (uint32_t)(c % STAGES) * 32768u;
        const int k0 = c << 5;
        #pragma unroll
        for (int p = 0; p < 4; p++) {
            int l = p * 256 + tid; int r = l >> 3, u = l & 7;
            const float* g = A + (size_t)(row0 + r) * K + k0 + u * 4;
            uint32_t off = (uint32_t)r * 128u + (uint32_t)((u ^ (r & 7)) << 4);
            asm volatile("cp.async.cg.shared.global [%0], [%1], 16;" :: "r"(st + off), "l"(g));
        }
        #pragma unroll
        for (int p = 0; p < 4; p++) {
            int l = p * 256 + tid; int r = l >> 3, u = l & 7;
            const float* g = Bt + (size_t)(col0 + r) * K + k0 + u * 4;
            uint32_t off = 16384u + (uint32_t)r * 128u + (uint32_t)((u ^ (r & 7)) << 4);
            asm volatile("cp.async.cg.shared.global [%0], [%1], 16;" :: "r"(st + off), "l"(g));
        }
        asm volatile("cp.async.commit_group;" ::: "memory");
    };

    // lane-derived ldmatrix address components
    const uint32_t swz   = lid & 7;
    const uint32_t a_row = (lid & 7) + ((lid >> 3) & 1) * 8;
    const uint32_t a_khi = (lid >> 4);
    const uint32_t b_row = ((lid >> 4) & 1) * 8 + (lid & 7);
    const uint32_t b_khi = (lid >> 3) & 1;

    float acc[2][8][4];
    #pragma unroll
    for (int mt = 0; mt < 2; mt++)
        #pragma unroll
        for (int nt = 0; nt < 8; nt++)
            #pragma unroll
            for (int j = 0; j < 4; j++) acc[mt][nt][j] = 0.f;

    // prologue: STAGES-1 chunks in flight
    for (int c = 0; c < STAGES - 1; c++) load_chunk(c);

    for (int c = 0; c < NC; c++) {
        asm volatile("cp.async.wait_group %0;" :: "n"(STAGES - 2) : "memory");
        __syncthreads();   // also protects the stage about to be overwritten below

        if (c + STAGES - 1 < NC) load_chunk(c + STAGES - 1);
        else asm volatile("cp.async.commit_group;" ::: "memory");

        const uint32_t sA = sb + (uint32_t)(c % STAGES) * 32768u;
        const uint32_t sB = sA + 16384u;

        #pragma unroll
        for (int ks = 0; ks < 4; ks++) {
            uint32_t a[2][4];
            #pragma unroll
            for (int mt = 0; mt < 2; mt++) {
                uint32_t row = (uint32_t)(wm * 32 + mt * 16) + a_row;
                uint32_t kg  = (uint32_t)(ks * 2) + a_khi;
                ldsm4(a[mt], sA + row * 128u + ((kg ^ swz) << 4));
            }
            uint32_t b[8][2];
            #pragma unroll
            for (int i = 0; i < 4; i++) {
                uint32_t row = (uint32_t)(wn * 64 + i * 16) + b_row;
                uint32_t kg  = (uint32_t)(ks * 2) + b_khi;
                uint32_t r4[4];
                ldsm4(r4, sB + row * 128u + ((kg ^ swz) << 4));
                b[2*i][0]   = r4[0]; b[2*i][1]   = r4[1];
                b[2*i+1][0] = r4[2]; b[2*i+1][1] = r4[3];
            }
            #pragma unroll
            for (int mt = 0; mt < 2; mt++)
                #pragma unroll
                for (int nt = 0; nt < 8; nt++)
                    mma_tf32(acc[mt][nt], a[mt], b[nt]);
        }
        // no trailing barrier: next iteration's post-wait __syncthreads protects reuse
    }

    // ---------------- epilogue ----------------
    const int cbase = col0 + wn * 64 + (lid & 3) * 2;
    float2 bf[8];
    #pragma unroll
    for (int nt = 0; nt < 8; nt++) bf[nt] = *(const float2*)(bias + cbase + nt * 8);

    #pragma unroll
    for (int mt = 0; mt < 2; mt++) {
        #pragma unroll
        for (int h = 0; h < 2; h++) {
            int m = row0 + wm * 32 + mt * 16 + h * 8 + (lid >> 2);
            int drow = (EPI == EPI_SCATTER) ? map_row(m) : m;
            float* cp = C + (size_t)drow * N + cbase;
            const float* rp = (EPI == EPI_SCATTER || EPI == EPI_RESID)
                              ? (R + (size_t)drow * N + cbase) : nullptr;
            #pragma unroll
            for (int nt = 0; nt < 8; nt++) {
                float vx = acc[mt][nt][h * 2 + 0] + bf[nt].x;
                float vy = acc[mt][nt][h * 2 + 1] + bf[nt].y;
                if (EPI == EPI_GELU) {
                    float u = vx;
                    vx = 0.5f * u * (1.0f + tanhf(0.7978845608f * (u + 0.044715f * u * u * u)));
                    vx = to_tf32(vx);
                    u = vy;
                    vy = 0.5f * u * (1.0f + tanhf(0.7978845608f * (u + 0.044715f * u * u * u)));
                    vy = to_tf32(vy);
                }
                if (EPI == EPI_SCATTER || EPI == EPI_RESID) {
                    float2 rv = *(const float2*)(rp + nt * 8);
                    vx += rv.x; vy += rv.y;
                }
                *(float2*)(cp + nt * 8) = make_float2(vx, vy);
            }
        }
    }
}

// ---------------- windowed attention ----------------
__global__ __launch_bounds__(256) void attn_kernel(const float* __restrict__ qkv,
                                                   const float* __restrict__ rpbt,
                                                   float* __restrict__ out)
{
    int w = blockIdx.x >> 4;
    int h = blockIdx.x & 15;
    __shared__ float q[NTOK][33], k[NTOK][33], v[NTOK][33];
    __shared__ float att[NTOK][52];
    int tid = threadIdx.x;

    const float* base = qkv + (size_t)w * NTOK * (3 * Cc) + h * 32;
    for (int p = tid; p < NTOK * 32; p += 256) {
        int i = p >> 5, d = p & 31;
        const float* rp = base + (size_t)i * (3 * Cc) + d;
        q[i][d] = rp[0] * 0.1767766953f;
        k[i][d] = rp[512];
        v[i][d] = rp[1024];
    }
    __syncthreads();

    int wi = w & 15;
    int wh = wi >> 2, ww = wi & 3;

    for (int p = tid; p < NTOK * NTOK; p += 256) {
        int i = p / NTOK, j = p - i * NTOK;
        float s = 0.f;
        #pragma unroll
        for (int d = 0; d < 32; d++) s += q[i][d] * k[j][d];
        int ri = i / 7, ci = i - ri * 7;
        int rj = j / 7, cj = j - rj * 7;
        int bidx = (ri - rj + 6) * 13 + (ci - cj + 6);
        s += rpbt[bidx * NHEADS + h];
        int hi = wh * 7 + ri, wwi = ww * 7 + ci;
        int hj = wh * 7 + rj, wwj = ww * 7 + cj;
        int cnti = (hi >= 25 ? 2 : (hi >= 21 ? 1 : 0)) * 3 + (wwi >= 25 ? 2 : (wwi >= 21 ? 1 : 0));
        int cntj = (hj >= 25 ? 2 : (hj >= 21 ? 1 : 0)) * 3 + (wwj >= 25 ? 2 : (wwj >= 21 ? 1 : 0));
        if (cnti != cntj) s -= 100.0f;
        att[i][j] = s;
    }
    __syncthreads();

    if (tid < NTOK) {
        float mx = -1e30f;
        #pragma unroll
        for (int j = 0; j < NTOK; j++) mx = fmaxf(mx, att[tid][j]);
        float sum = 0.f;
        #pragma unroll
        for (int j = 0; j < NTOK; j++) {
            float e = __expf(att[tid][j] - mx);
            att[tid][j] = e;
            sum += e;
        }
        float inv = 1.0f / sum;
        #pragma unroll
        for (int j = 0; j < NTOK; j++) att[tid][j] *= inv;
    }
    __syncthreads();

    float* ob = out + (size_t)w * NTOK * Cc + h * 32;
    for (int p = tid; p < NTOK * 32; p += 256) {
        int i = p >> 5, d = p & 31;
        float s = 0.f;
        #pragma unroll
        for (int j = 0; j < NTOK; j++) s += att[i][j] * v[j][d];
        ob[(size_t)i * Cc + d] = to_tf32(s);
    }
}

// ---------------- host launch ----------------
extern "C" void kernel_launch(void* const* d_in, const int* in_sizes, int n_in,
                              void* d_out, int out_size)
{
    const float* x      = (const float*)d_in[0];
    const float* qkv_w  = (const float*)d_in[1];
    const float* qkv_b  = (const float*)d_in[2];
    const float* proj_w = (const float*)d_in[3];
    const float* proj_b = (const float*)d_in[4];
    const float* rpbt   = (const float*)d_in[5];
    const float* n1_s   = (const float*)d_in[6];
    const float* n1_b   = (const float*)d_in[7];
    const float* n2_s   = (const float*)d_in[8];
    const float* n2_b   = (const float*)d_in[9];
    const float* fc1_w  = (const float*)d_in[10];
    const float* fc1_b  = (const float*)d_in[11];
    const float* fc2_w  = (const float*)d_in[12];
    const float* fc2_b  = (const float*)d_in[13];
    float* outp = (float*)d_out;

    float *p_win, *p_qkv, *p_att, *p_x2, *p_ln2, *p_hid;
    float *p_wqkvT, *p_wprojT, *p_wfc1T, *p_wfc2T;
    cudaGetSymbolAddress((void**)&p_win, g_win);
    cudaGetSymbolAddress((void**)&p_qkv, g_qkv);
    cudaGetSymbolAddress((void**)&p_att, g_att);
    cudaGetSymbolAddress((void**)&p_x2,  g_x2);
    cudaGetSymbolAddress((void**)&p_ln2, g_ln2);
    cudaGetSymbolAddress((void**)&p_hid, g_hid);
    cudaGetSymbolAddress((void**)&p_wqkvT, g_wqkvT);
    cudaGetSymbolAddress((void**)&p_wprojT, g_wprojT);
    cudaGetSymbolAddress((void**)&p_wfc1T, g_wfc1T);
    cudaGetSymbolAddress((void**)&p_wfc2T, g_wfc2T);

    const int SMEM_BYTES = STAGES * 32768;   // 96 KB -> 2 CTAs/SM
    cudaFuncSetAttribute(gemm_tc<EPI_BIAS>,    cudaFuncAttributeMaxDynamicSharedMemorySize, SMEM_BYTES);
    cudaFuncSetAttribute(gemm_tc<EPI_SCATTER>, cudaFuncAttributeMaxDynamicSharedMemorySize, SMEM_BYTES);
    cudaFuncSetAttribute(gemm_tc<EPI_GELU>,    cudaFuncAttributeMaxDynamicSharedMemorySize, SMEM_BYTES);
    cudaFuncSetAttribute(gemm_tc<EPI_RESID>,   cudaFuncAttributeMaxDynamicSharedMemorySize, SMEM_BYTES);

    // 0) weight transposes (tf32-rounded), [K][N] -> [N][K]
    transpose_rt<<<dim3(3*Cc/32, Cc/32),  256>>>(qkv_w,  p_wqkvT,  Cc,   3*Cc);
    transpose_rt<<<dim3(Cc/32,   Cc/32),  256>>>(proj_w, p_wprojT, Cc,   Cc);
    transpose_rt<<<dim3(MLPH/32, Cc/32),  256>>>(fc1_w,  p_wfc1T,  Cc,   MLPH);
    transpose_rt<<<dim3(Cc/32,   MLPH/32),256>>>(fc2_w,  p_wfc2T,  MLPH, Cc);

    // 1) LN1 + shift + window partition (tf32-rounded A)
    ln_kernel<true, true><<<MROWS, 128>>>(x, n1_s, n1_b, p_win);

    // 2) QKV GEMM
    gemm_tc<EPI_BIAS><<<dim3(3*Cc/128, MROWS/128), 256, SMEM_BYTES>>>(
        p_win, p_wqkvT, qkv_b, nullptr, p_qkv, MROWS, 3*Cc, Cc);

    // 3) windowed attention
    attn_kernel<<<BWIN * NHEADS, 256>>>(p_qkv, rpbt, p_att);

    // 4) proj GEMM + window-reverse scatter + residual
    gemm_tc<EPI_SCATTER><<<dim3(Cc/128, MROWS/128), 256, SMEM_BYTES>>>(
        p_att, p_wprojT, proj_b, x, p_x2, MROWS, Cc, Cc);

    // 5) LN2 (tf32-rounded A)
    ln_kernel<false, true><<<MROWS, 128>>>(p_x2, n2_s, n2_b, p_ln2);

    // 6) fc1 GEMM + GELU (tf32-rounded out)
    gemm_tc<EPI_GELU><<<dim3(MLPH/128, MROWS/128), 256, SMEM_BYTES>>>(
        p_ln2, p_wfc1T, fc1_b, nullptr, p_hid, MROWS, MLPH, Cc);

    // 7) fc2 GEMM + bias + residual -> out
    gemm_tc<EPI_RESID><<<dim3(Cc/128, MROWS/128), 256, SMEM_BYTES>>>(
        p_hid, p_wfc2T, fc2_b, p_x2, outp, MROWS, Cc, MLPH);
}

// round 5
// speedup vs baseline: 4.9344x; 1.4453x over previous
#include <cuda_runtime.h>
#include <cuda.h>
#include <cuda_fp16.h>
#include <math.h>
#include <stdint.h>

// ---------------- problem constants ----------------
#define Bv     64
#define Hd     28
#define Wd     28
#define Cc     512
#define NHEADS 16
#define WIN    7
#define SHIFTV 3
#define NTOK   49
#define NWIN   16
#define BWIN   (Bv*NWIN)
#define MROWS  (BWIN*NTOK)   // 50176
#define MLPH   2048
#define STAGES 3

// ---------------- scratch (allocation-free: device globals) ----------------
__device__ __half g_win[(size_t)MROWS * Cc];
__device__ __half g_qkv[(size_t)MROWS * 3 * Cc];
__device__ __half g_att[(size_t)MROWS * Cc];
__device__ float  g_x2 [(size_t)MROWS * Cc];          // fp32 residual
__device__ __half g_ln2[(size_t)MROWS * Cc];
__device__ __half g_hid[(size_t)MROWS * MLPH];
// transposed fp16 weights, [N][K] K-major
__device__ __half g_wqkvT[(size_t)(3*Cc) * Cc];
__device__ __half g_wprojT[(size_t)Cc * Cc];
__device__ __half g_wfc1T[(size_t)MLPH * Cc];
__device__ __half g_wfc2T[(size_t)Cc * MLPH];

// ---------------- helpers ----------------
__device__ __forceinline__ uint32_t smem_u32(const void* p) {
    uint32_t a;
    asm("{ .reg .u64 t; cvta.to.shared.u64 t, %1; cvt.u32.u64 %0, t; }" : "=r"(a) : "l"(p));
    return a;
}
__device__ __forceinline__ void ldsm4(uint32_t* r, uint32_t addr) {
    asm volatile("ldmatrix.sync.aligned.m8n8.x4.b16 {%0,%1,%2,%3}, [%4];"
                 : "=r"(r[0]), "=r"(r[1]), "=r"(r[2]), "=r"(r[3]) : "r"(addr));
}
__device__ __forceinline__ void mma_f16(float* c, const uint32_t* a, const uint32_t* b) {
    asm volatile("mma.sync.aligned.m16n8k16.row.col.f32.f16.f16.f32 "
                 "{%0,%1,%2,%3}, {%4,%5,%6,%7}, {%8,%9}, {%0,%1,%2,%3};"
                 : "+f"(c[0]), "+f"(c[1]), "+f"(c[2]), "+f"(c[3])
                 : "r"(a[0]), "r"(a[1]), "r"(a[2]), "r"(a[3]), "r"(b[0]), "r"(b[1]));
}

// ---------------- row map: window token -> original (B, H*W) row ----------------
__device__ __forceinline__ int map_row(int m) {
    int w = m / NTOK, n = m - w * NTOK;
    int b  = w >> 4, wi = w & 15;
    int wh = wi >> 2, ww = wi & 3;
    int r  = n / 7,  c  = n - r * 7;
    int oh = wh * 7 + r + SHIFTV; if (oh >= Hd) oh -= Hd;
    int ow = ww * 7 + c + SHIFTV; if (ow >= Wd) ow -= Wd;
    return b * (Hd * Wd) + oh * Wd + ow;
}

// ---------------- LayerNorm: fp32 in -> fp16 out ----------------
template<bool GATHER>
__global__ __launch_bounds__(128) void ln_kernel(const float* __restrict__ x,
                                                 const float* __restrict__ sc,
                                                 const float* __restrict__ bi,
                                                 __half* __restrict__ out)
{
    int row = blockIdx.x;
    int src = GATHER ? map_row(row) : row;
    int t = threadIdx.x;
    float4 v = ((const float4*)(x + (size_t)src * Cc))[t];
    float s = v.x + v.y + v.z + v.w;
    float q = v.x*v.x + v.y*v.y + v.z*v.z + v.w*v.w;
    #pragma unroll
    for (int o = 16; o; o >>= 1) {
        s += __shfl_xor_sync(0xffffffffu, s, o);
        q += __shfl_xor_sync(0xffffffffu, q, o);
    }
    __shared__ float ss[4], qq[4], stat[2];
    int wid = t >> 5;
    if ((t & 31) == 0) { ss[wid] = s; qq[wid] = q; }
    __syncthreads();
    if (t == 0) {
        float S = ss[0] + ss[1] + ss[2] + ss[3];
        float Q = qq[0] + qq[1] + qq[2] + qq[3];
        float mean = S * (1.0f / Cc);
        float var  = Q * (1.0f / Cc) - mean * mean;
        stat[0] = mean; stat[1] = rsqrtf(var + 1e-5f);
    }
    __syncthreads();
    float mean = stat[0], rstd = stat[1];
    float4 sv = ((const float4*)sc)[t];
    float4 bv = ((const float4*)bi)[t];
    __half2 h0 = __floats2half2_rn((v.x - mean) * rstd * sv.x + bv.x,
                                   (v.y - mean) * rstd * sv.y + bv.y);
    __half2 h1 = __floats2half2_rn((v.z - mean) * rstd * sv.z + bv.z,
                                   (v.w - mean) * rstd * sv.w + bv.w);
    uint2 pk = make_uint2(*(uint32_t*)&h0, *(uint32_t*)&h1);
    ((uint2*)(out + (size_t)row * Cc))[t] = pk;
}

// ---------------- weight transpose [K][N] fp32 -> [N][K] fp16 ----------------
__global__ __launch_bounds__(256) void transpose_h(const float* __restrict__ in,
                                                   __half* __restrict__ out, int K, int N)
{
    __shared__ float t[32][33];
    int k0 = blockIdx.y * 32, n0 = blockIdx.x * 32;
    int tx = threadIdx.x & 31, ty = threadIdx.x >> 5;
    #pragma unroll
    for (int i = ty; i < 32; i += 8) t[i][tx] = in[(size_t)(k0 + i) * N + n0 + tx];
    __syncthreads();
    #pragma unroll
    for (int i = ty; i < 32; i += 8)
        out[(size_t)(n0 + i) * K + k0 + tx] = __float2half(t[tx][i]);
}

// ---------------- fp16 mma.sync GEMM: C[M,N] = A[M,K] @ Bt[N,K]^T + epi ----------------
// CTA tile 128x128, k-chunk 64, 8 warps (4m x 2n), warp tile 32x64, 3-stage, 2 CTAs/SM.
enum { EPI_BIAS = 0, EPI_SCATTER = 1, EPI_GELU = 2, EPI_RESID = 3 };

template<int EPI, typename TOUT>
__global__ __launch_bounds__(256, 2) void gemm_tc(const __half* __restrict__ A,
                                                  const __half* __restrict__ Bt,
                                                  const float* __restrict__ bias,
                                                  const float* __restrict__ R,
                                                  TOUT* __restrict__ C,
                                                  int M, int N, int K)
{
    extern __shared__ char smem[];
    const uint32_t sb = smem_u32(smem);
    const int tid = threadIdx.x;
    const int wid = tid >> 5;
    const int lid = tid & 31;
    const int wm = wid & 3;
    const int wn = wid >> 2;

    const int row0 = blockIdx.y * 128;
    const int col0 = blockIdx.x * 128;
    const int NC = K >> 6;   // 64 halfs per chunk

    // cp.async: per operand per chunk 128 rows x 64 halfs (128B rows), 16B per op
    auto load_chunk = [&](int c) {
        const uint32_t st = sb + (uint32_t)(c % STAGES) * 32768u;
        const int k0 = c << 6;
        #pragma unroll
        for (int p = 0; p < 4; p++) {
            int l = p * 256 + tid; int r = l >> 3, u = l & 7;
            const __half* g = A + (size_t)(row0 + r) * K + k0 + u * 8;
            uint32_t off = (uint32_t)r * 128u + (uint32_t)((u ^ (r & 7)) << 4);
            asm volatile("cp.async.cg.shared.global [%0], [%1], 16;" :: "r"(st + off), "l"(g));
        }
        #pragma unroll
        for (int p = 0; p < 4; p++) {
            int l = p * 256 + tid; int r = l >> 3, u = l & 7;
            const __half* g = Bt + (size_t)(col0 + r) * K + k0 + u * 8;
            uint32_t off = 16384u + (uint32_t)r * 128u + (uint32_t)((u ^ (r & 7)) << 4);
            asm volatile("cp.async.cg.shared.global [%0], [%1], 16;" :: "r"(st + off), "l"(g));
        }
        asm volatile("cp.async.commit_group;" ::: "memory");
    };

    const uint32_t swz   = lid & 7;
    const uint32_t a_row = (lid & 7) + ((lid >> 3) & 1) * 8;
    const uint32_t a_khi = (lid >> 4);
    const uint32_t b_row = ((lid >> 4) & 1) * 8 + (lid & 7);
    const uint32_t b_khi = (lid >> 3) & 1;

    float acc[2][8][4];
    #pragma unroll
    for (int mt = 0; mt < 2; mt++)
        #pragma unroll
        for (int nt = 0; nt < 8; nt++)
            #pragma unroll
            for (int j = 0; j < 4; j++) acc[mt][nt][j] = 0.f;

    for (int c = 0; c < STAGES - 1; c++) load_chunk(c);

    for (int c = 0; c < NC; c++) {
        asm volatile("cp.async.wait_group %0;" :: "n"(STAGES - 2) : "memory");
        __syncthreads();

        if (c + STAGES - 1 < NC) load_chunk(c + STAGES - 1);
        else asm volatile("cp.async.commit_group;" ::: "memory");

        const uint32_t sA = sb + (uint32_t)(c % STAGES) * 32768u;
        const uint32_t sB = sA + 16384u;

        #pragma unroll
        for (int ks = 0; ks < 4; ks++) {  // k-step = 16 halfs = 2 x 16B units
            uint32_t a[2][4];
            #pragma unroll
            for (int mt = 0; mt < 2; mt++) {
                uint32_t row = (uint32_t)(wm * 32 + mt * 16) + a_row;
                uint32_t kg  = (uint32_t)(ks * 2) + a_khi;
                ldsm4(a[mt], sA + row * 128u + ((kg ^ swz) << 4));
            }
            uint32_t b[8][2];
            #pragma unroll
            for (int i = 0; i < 4; i++) {
                uint32_t row = (uint32_t)(wn * 64 + i * 16) + b_row;
                uint32_t kg  = (uint32_t)(ks * 2) + b_khi;
                uint32_t r4[4];
                ldsm4(r4, sB + row * 128u + ((kg ^ swz) << 4));
                b[2*i][0]   = r4[0]; b[2*i][1]   = r4[1];
                b[2*i+1][0] = r4[2]; b[2*i+1][1] = r4[3];
            }
            #pragma unroll
            for (int mt = 0; mt < 2; mt++)
                #pragma unroll
                for (int nt = 0; nt < 8; nt++)
                    mma_f16(acc[mt][nt], a[mt], b[nt]);
        }
    }

    // ---------------- epilogue ----------------
    const int cbase = col0 + wn * 64 + (lid & 3) * 2;
    float2 bf[8];
    #pragma unroll
    for (int nt = 0; nt < 8; nt++) bf[nt] = *(const float2*)(bias + cbase + nt * 8);

    #pragma unroll
    for (int mt = 0; mt < 2; mt++) {
        #pragma unroll
        for (int h = 0; h < 2; h++) {
            int m = row0 + wm * 32 + mt * 16 + h * 8 + (lid >> 2);
            int drow = (EPI == EPI_SCATTER) ? map_row(m) : m;
            TOUT* cp = C + (size_t)drow * N + cbase;
            const float* rp = (EPI == EPI_SCATTER || EPI == EPI_RESID)
                              ? (R + (size_t)drow * N + cbase) : nullptr;
            #pragma unroll
            for (int nt = 0; nt < 8; nt++) {
                float vx = acc[mt][nt][h * 2 + 0] + bf[nt].x;
                float vy = acc[mt][nt][h * 2 + 1] + bf[nt].y;
                if (EPI == EPI_GELU) {
                    float u = vx;
                    vx = 0.5f * u * (1.0f + tanhf(0.7978845608f * (u + 0.044715f * u * u * u)));
                    u = vy;
                    vy = 0.5f * u * (1.0f + tanhf(0.7978845608f * (u + 0.044715f * u * u * u)));
                }
                if (EPI == EPI_SCATTER || EPI == EPI_RESID) {
                    float2 rv = *(const float2*)(rp + nt * 8);
                    vx += rv.x; vy += rv.y;
                }
                if (sizeof(TOUT) == 2) {
                    __half2 hv = __floats2half2_rn(vx, vy);
                    *(__half2*)((__half*)cp + nt * 8) = hv;
                } else {
                    *(float2*)((float*)cp + nt * 8) = make_float2(vx, vy);
                }
            }
        }
    }
}

// ---------------- windowed attention: fp16 qkv in, fp16 out, fp32 math ----------------
__global__ __launch_bounds__(256) void attn_kernel(const __half* __restrict__ qkv,
                                                   const float* __restrict__ rpbt,
                                                   __half* __restrict__ out)
{
    int w = blockIdx.x >> 4;
    int h = blockIdx.x & 15;
    __shared__ float q[NTOK][33], k[NTOK][33], v[NTOK][33];
    __shared__ float att[NTOK][52];
    int tid = threadIdx.x;

    const __half* base = qkv + (size_t)w * NTOK * (3 * Cc) + h * 32;
    for (int p = tid; p < NTOK * 32; p += 256) {
        int i = p >> 5, d = p & 31;
        const __half* rp = base + (size_t)i * (3 * Cc) + d;
        q[i][d] = __half2float(rp[0]) * 0.1767766953f;
        k[i][d] = __half2float(rp[512]);
        v[i][d] = __half2float(rp[1024]);
    }
    __syncthreads();

    int wi = w & 15;
    int wh = wi >> 2, ww = wi & 3;

    for (int p = tid; p < NTOK * NTOK; p += 256) {
        int i = p / NTOK, j = p - i * NTOK;
        float s = 0.f;
        #pragma unroll
        for (int d = 0; d < 32; d++) s += q[i][d] * k[j][d];
        int ri = i / 7, ci = i - ri * 7;
        int rj = j / 7, cj = j - rj * 7;
        int bidx = (ri - rj + 6) * 13 + (ci - cj + 6);
        s += rpbt[bidx * NHEADS + h];
        int hi = wh * 7 + ri, wwi = ww * 7 + ci;
        int hj = wh * 7 + rj, wwj = ww * 7 + cj;
        int cnti = (hi >= 25 ? 2 : (hi >= 21 ? 1 : 0)) * 3 + (wwi >= 25 ? 2 : (wwi >= 21 ? 1 : 0));
        int cntj = (hj >= 25 ? 2 : (hj >= 21 ? 1 : 0)) * 3 + (wwj >= 25 ? 2 : (wwj >= 21 ? 1 : 0));
        if (cnti != cntj) s -= 100.0f;
        att[i][j] = s;
    }
    __syncthreads();

    if (tid < NTOK) {
        float mx = -1e30f;
        #pragma unroll
        for (int j = 0; j < NTOK; j++) mx = fmaxf(mx, att[tid][j]);
        float sum = 0.f;
        #pragma unroll
        for (int j = 0; j < NTOK; j++) {
            float e = __expf(att[tid][j] - mx);
            att[tid][j] = e;
            sum += e;
        }
        float inv = 1.0f / sum;
        #pragma unroll
        for (int j = 0; j < NTOK; j++) att[tid][j] *= inv;
    }
    __syncthreads();

    __half* ob = out + (size_t)w * NTOK * Cc + h * 32;
    for (int p = tid; p < NTOK * 32; p += 256) {
        int i = p >> 5, d = p & 31;
        float s = 0.f;
        #pragma unroll
        for (int j = 0; j < NTOK; j++) s += att[i][j] * v[j][d];
        ob[(size_t)i * Cc + d] = __float2half(s);
    }
}

// ---------------- host launch ----------------
extern "C" void kernel_launch(void* const* d_in, const int* in_sizes, int n_in,
                              void* d_out, int out_size)
{
    const float* x      = (const float*)d_in[0];
    const float* qkv_w  = (const float*)d_in[1];
    const float* qkv_b  = (const float*)d_in[2];
    const float* proj_w = (const float*)d_in[3];
    const float* proj_b = (const float*)d_in[4];
    const float* rpbt   = (const float*)d_in[5];
    const float* n1_s   = (const float*)d_in[6];
    const float* n1_b   = (const float*)d_in[7];
    const float* n2_s   = (const float*)d_in[8];
    const float* n2_b   = (const float*)d_in[9];
    const float* fc1_w  = (const float*)d_in[10];
    const float* fc1_b  = (const float*)d_in[11];
    const float* fc2_w  = (const float*)d_in[12];
    const float* fc2_b  = (const float*)d_in[13];
    float* outp = (float*)d_out;

    __half *p_win, *p_qkv, *p_att, *p_ln2, *p_hid;
    __half *p_wqkvT, *p_wprojT, *p_wfc1T, *p_wfc2T;
    float *p_x2;
    cudaGetSymbolAddress((void**)&p_win, g_win);
    cudaGetSymbolAddress((void**)&p_qkv, g_qkv);
    cudaGetSymbolAddress((void**)&p_att, g_att);
    cudaGetSymbolAddress((void**)&p_x2,  g_x2);
    cudaGetSymbolAddress((void**)&p_ln2, g_ln2);
    cudaGetSymbolAddress((void**)&p_hid, g_hid);
    cudaGetSymbolAddress((void**)&p_wqkvT, g_wqkvT);
    cudaGetSymbolAddress((void**)&p_wprojT, g_wprojT);
    cudaGetSymbolAddress((void**)&p_wfc1T, g_wfc1T);
    cudaGetSymbolAddress((void**)&p_wfc2T, g_wfc2T);

    const int SMEM_BYTES = STAGES * 32768;   // 96 KB -> 2 CTAs/SM
    cudaFuncSetAttribute((const void*)gemm_tc<EPI_BIAS, __half>,   cudaFuncAttributeMaxDynamicSharedMemorySize, SMEM_BYTES);
    cudaFuncSetAttribute((const void*)gemm_tc<EPI_SCATTER, float>, cudaFuncAttributeMaxDynamicSharedMemorySize, SMEM_BYTES);
    cudaFuncSetAttribute((const void*)gemm_tc<EPI_GELU, __half>,   cudaFuncAttributeMaxDynamicSharedMemorySize, SMEM_BYTES);
    cudaFuncSetAttribute((const void*)gemm_tc<EPI_RESID, float>,   cudaFuncAttributeMaxDynamicSharedMemorySize, SMEM_BYTES);

    // 0) weight transposes fp32 -> fp16 [N][K]
    transpose_h<<<dim3(3*Cc/32, Cc/32),  256>>>(qkv_w,  p_wqkvT,  Cc,   3*Cc);
    transpose_h<<<dim3(Cc/32,   Cc/32),  256>>>(proj_w, p_wprojT, Cc,   Cc);
    transpose_h<<<dim3(MLPH/32, Cc/32),  256>>>(fc1_w,  p_wfc1T,  Cc,   MLPH);
    transpose_h<<<dim3(Cc/32,   MLPH/32),256>>>(fc2_w,  p_wfc2T,  MLPH, Cc);

    // 1) LN1 + shift + window partition -> fp16
    ln_kernel<true><<<MROWS, 128>>>(x, n1_s, n1_b, p_win);

    // 2) QKV GEMM -> fp16
    gemm_tc<EPI_BIAS, __half><<<dim3(3*Cc/128, MROWS/128), 256, SMEM_BYTES>>>(
        p_win, p_wqkvT, qkv_b, nullptr, p_qkv, MROWS, 3*Cc, Cc);

    // 3) windowed attention -> fp16
    attn_kernel<<<BWIN * NHEADS, 256>>>(p_qkv, rpbt, p_att);

    // 4) proj GEMM + window-reverse scatter + residual -> fp32
    gemm_tc<EPI_SCATTER, float><<<dim3(Cc/128, MROWS/128), 256, SMEM_BYTES>>>(
        p_att, p_wprojT, proj_b, x, p_x2, MROWS, Cc, Cc);

    // 5) LN2 -> fp16
    ln_kernel<false><<<MROWS, 128>>>(p_x2, n2_s, n2_b, p_ln2);

    // 6) fc1 GEMM + GELU -> fp16
    gemm_tc<EPI_GELU, __half><<<dim3(MLPH/128, MROWS/128), 256, SMEM_BYTES>>>(
        p_ln2, p_wfc1T, fc1_b, nullptr, p_hid, MROWS, MLPH, Cc);

    // 7) fc2 GEMM + bias + residual -> fp32 out
    gemm_tc<EPI_RESID, float><<<dim3(Cc/128, MROWS/128), 256, SMEM_BYTES>>>(
        p_hid, p_wfc2T, fc2_b, p_x2, outp, MROWS, Cc, MLPH);
}